// round 1
// baseline (speedup 1.0000x reference)
#include <cuda_runtime.h>
#include <math.h>
#include <float.h>

#define DDIM 1024
#define NKEYS 32768

// Scratch (no allocations allowed in kernel_launch)
__device__ float g_q[DDIM];
__device__ float g_scores[NKEYS];
__device__ int   g_defk = 10;   // fallback if k is not passed as an input

// ---------------------------------------------------------------------------
// K1: q = Wq @ query + bq   (warp per output row, float4 loads)
// ---------------------------------------------------------------------------
__global__ void qproj_kernel(const float* __restrict__ query,
                             const float* __restrict__ Wq,
                             const float* __restrict__ bq) {
    int gwarp = (blockIdx.x * blockDim.x + threadIdx.x) >> 5;
    int lane  = threadIdx.x & 31;
    if (gwarp >= DDIM) return;
    const float4* wrow = (const float4*)(Wq + (size_t)gwarp * DDIM);
    const float4* qv   = (const float4*)query;
    float s = 0.f;
#pragma unroll
    for (int it = 0; it < 8; it++) {
        int idx = it * 32 + lane;
        float4 w = wrow[idx];
        float4 x = __ldg(&qv[idx]);
        s += w.x * x.x + w.y * x.y + w.z * x.z + w.w * x.w;
    }
#pragma unroll
    for (int off = 16; off; off >>= 1) s += __shfl_xor_sync(0xffffffffu, s, off);
    if (lane == 0) g_q[gwarp] = s + bq[gwarp];
}

// ---------------------------------------------------------------------------
// K2: scores[i] = keys[i,:] . q   (warp per row; dominant 128MB stream)
// ---------------------------------------------------------------------------
__global__ void scores_kernel(const float* __restrict__ keys) {
    int gwarp = (blockIdx.x * blockDim.x + threadIdx.x) >> 5;
    int lane  = threadIdx.x & 31;
    const float4* krow = (const float4*)(keys + (size_t)gwarp * DDIM);
    const float4* qv   = (const float4*)g_q;
    float s = 0.f;
#pragma unroll
    for (int it = 0; it < 8; it++) {
        int idx = it * 32 + lane;
        float4 kk = krow[idx];
        float4 qq = __ldg(&qv[idx]);
        s += kk.x * qq.x + kk.y * qq.y + kk.z * qq.z + kk.w * qq.w;
    }
#pragma unroll
    for (int off = 16; off; off >>= 1) s += __shfl_xor_sync(0xffffffffu, s, off);
    if (lane == 0) g_scores[gwarp] = s;
}

// ---------------------------------------------------------------------------
// K3: softmax stats + top-k + gather, single block of 1024 threads.
// Each thread caches its 32 scores in registers -> top-k passes are
// register-local (no repeated L2 traffic over the score array).
// Output layout: out[0 .. k*D)  = values[idx_t, :]  (t-major)
//                out[k*D .. k*D+k) = top_w
// ---------------------------------------------------------------------------
__global__ void __launch_bounds__(1024, 1)
topk_gather_kernel(const float* __restrict__ values,
                   const int* __restrict__ kp,
                   float* __restrict__ out) {
    const int tid  = threadIdx.x;
    const int lane = tid & 31;
    const int wid  = tid >> 5;
    const float ISD = 0.03125f;  // 1/sqrt(1024)

    __shared__ float s_red[32];
    __shared__ int   s_redi[32];
    __shared__ float s_M, s_S;
    __shared__ int   s_widx;
    __shared__ int   s_rows[32];

    // Load the whole score array into the register file of this block.
    float v[32];
#pragma unroll
    for (int j = 0; j < 32; j++) v[j] = g_scores[j * 1024 + tid];

    // ---- global max ----
    float m = -FLT_MAX;
#pragma unroll
    for (int j = 0; j < 32; j++) m = fmaxf(m, v[j]);
#pragma unroll
    for (int off = 16; off; off >>= 1) m = fmaxf(m, __shfl_xor_sync(0xffffffffu, m, off));
    if (lane == 0) s_red[wid] = m;
    __syncthreads();
    if (wid == 0) {
        float mm = s_red[lane];
#pragma unroll
        for (int off = 16; off; off >>= 1) mm = fmaxf(mm, __shfl_xor_sync(0xffffffffu, mm, off));
        if (lane == 0) s_M = mm;
    }
    __syncthreads();
    const float M = s_M;

    // ---- sum of exp ----
    float ssum = 0.f;
#pragma unroll
    for (int j = 0; j < 32; j++) ssum += expf((v[j] - M) * ISD);
#pragma unroll
    for (int off = 16; off; off >>= 1) ssum += __shfl_xor_sync(0xffffffffu, ssum, off);
    if (lane == 0) s_red[wid] = ssum;
    __syncthreads();
    if (wid == 0) {
        float ss = s_red[lane];
#pragma unroll
        for (int off = 16; off; off >>= 1) ss += __shfl_xor_sync(0xffffffffu, ss, off);
        if (lane == 0) s_S = ss;
    }
    __syncthreads();
    const float S = s_S;

    const int k = *kp;

    // ---- k iterative argmax passes, register-local ----
    for (int t = 0; t < k; t++) {
        float best = -FLT_MAX;
        int bj = -1;
#pragma unroll
        for (int j = 0; j < 32; j++) {
            if (v[j] > best) { best = v[j]; bj = j; }
        }
        int bidx = (bj < 0) ? 0x7fffffff : (bj * 1024 + tid);
#pragma unroll
        for (int off = 16; off; off >>= 1) {
            float ov = __shfl_xor_sync(0xffffffffu, best, off);
            int   oi = __shfl_xor_sync(0xffffffffu, bidx, off);
            if (ov > best || (ov == best && oi < bidx)) { best = ov; bidx = oi; }
        }
        if (lane == 0) { s_red[wid] = best; s_redi[wid] = bidx; }
        __syncthreads();
        if (tid == 0) {
            float bb = -FLT_MAX;
            int bi = 0x7fffffff;
#pragma unroll
            for (int w = 0; w < 32; w++) {
                if (s_red[w] > bb || (s_red[w] == bb && s_redi[w] < bi)) {
                    bb = s_red[w]; bi = s_redi[w];
                }
            }
            s_rows[t] = bi;
            s_widx = bi;
            out[(size_t)k * DDIM + t] = expf((bb - M) * ISD) / S;
        }
        __syncthreads();
        const int win = s_widx;
        if ((win & 1023) == tid) {
            const int wj = win >> 10;
#pragma unroll
            for (int j = 0; j < 32; j++)
                if (j == wj) v[j] = -FLT_MAX;  // remove winner from my registers
        }
        // no extra barrier needed: marking is register-local; s_widx is not
        // rewritten until after the next iteration's post-s_red barrier.
    }
    __syncthreads();

    // ---- gather selected value rows (coalesced, 1024 threads == D) ----
    for (int t = 0; t < k; t++) {
        const int row = s_rows[t];
        out[(size_t)t * DDIM + tid] = values[(size_t)row * DDIM + tid];
    }
}

// ---------------------------------------------------------------------------
extern "C" void kernel_launch(void* const* d_in, const int* in_sizes, int n_in,
                              void* d_out, int out_size) {
    const float* query  = (const float*)d_in[0];   // [1024]
    const float* keys   = (const float*)d_in[1];   // [32768,1024]
    const float* values = (const float*)d_in[2];   // [32768,1024]
    const float* Wq     = (const float*)d_in[3];   // [1024,1024]
    const float* bq     = (const float*)d_in[4];   // [1024]

    const int* kp;
    if (n_in >= 6) {
        kp = (const int*)d_in[5];
    } else {
        void* p = nullptr;
        cudaGetSymbolAddress(&p, g_defk);
        kp = (const int*)p;
    }

    float* out = (float*)d_out;

    // K1: 1024 warps -> 128 blocks x 256 threads
    qproj_kernel<<<128, 256>>>(query, Wq, bq);
    // K2: 32768 warps -> 4096 blocks x 256 threads
    scores_kernel<<<4096, 256>>>(keys);
    // K3: one block, 1024 threads
    topk_gather_kernel<<<1, 1024>>>(values, kp, out);
    (void)in_sizes; (void)out_size;
}

// round 3
// speedup vs baseline: 1.1002x; 1.1002x over previous
#include <cuda_runtime.h>
#include <math.h>
#include <float.h>

#define DDIM 1024
#define NKEYS 32768

// Scratch (no allocations allowed in kernel_launch)
__device__ float g_q[DDIM];
__device__ float g_scores[NKEYS];
__device__ int   g_defk = 10;   // fallback if k is not passed as an input

// ---------------------------------------------------------------------------
// K1: q = Wq @ query + bq.  Block per output row, 256 threads, 1 float4 each.
// 1024 blocks -> plenty of parallelism for a 4MB latency-bound stream.
// ---------------------------------------------------------------------------
__global__ void __launch_bounds__(256)
qproj_kernel(const float* __restrict__ query,
             const float* __restrict__ Wq,
             const float* __restrict__ bq) {
    const int row  = blockIdx.x;
    const int tid  = threadIdx.x;
    const int lane = tid & 31;
    const int wid  = tid >> 5;

    const float4* wrow = (const float4*)(Wq + (size_t)row * DDIM);
    const float4* qv   = (const float4*)query;

    float4 w = wrow[tid];
    float4 x = __ldg(&qv[tid]);
    float s = w.x * x.x + w.y * x.y + w.z * x.z + w.w * x.w;

#pragma unroll
    for (int off = 16; off; off >>= 1) s += __shfl_xor_sync(0xffffffffu, s, off);

    __shared__ float sm[8];
    if (lane == 0) sm[wid] = s;
    __syncthreads();
    if (tid == 0) {
        float t = sm[0];
#pragma unroll
        for (int w8 = 1; w8 < 8; w8++) t += sm[w8];
        g_q[row] = t + bq[row];
    }
}

// ---------------------------------------------------------------------------
// K2: scores[i] = keys[i,:] . q   (warp per row; dominant 128MB stream)
// ---------------------------------------------------------------------------
__global__ void scores_kernel(const float* __restrict__ keys) {
    int gwarp = (blockIdx.x * blockDim.x + threadIdx.x) >> 5;
    int lane  = threadIdx.x & 31;
    const float4* krow = (const float4*)(keys + (size_t)gwarp * DDIM);
    const float4* qv   = (const float4*)g_q;
    float s = 0.f;
#pragma unroll
    for (int it = 0; it < 8; it++) {
        int idx = it * 32 + lane;
        float4 kk = krow[idx];
        float4 qq = __ldg(&qv[idx]);
        s += kk.x * qq.x + kk.y * qq.y + kk.z * qq.z + kk.w * qq.w;
    }
#pragma unroll
    for (int off = 16; off; off >>= 1) s += __shfl_xor_sync(0xffffffffu, s, off);
    if (lane == 0) g_scores[gwarp] = s;
}

// ---------------------------------------------------------------------------
// K3: softmax stats + top-k + gather, single block of 1024 threads.
// Scores cached in registers as 8 float4/thread; top-k passes register-local.
// Element index mapping: idx = j*4096 + tid*4 + c   (j = float4 slot, c = comp)
//   -> owning thread = (idx>>2)&1023, slot j = idx>>12, component c = idx&3.
// The flat element index IS the key/value row index (one score per row).
// Output layout: out[0 .. k*D)    = values[idx_t, :]  (t-major)
//                out[k*D .. k*D+k)= top_w
// ---------------------------------------------------------------------------
__global__ void __launch_bounds__(1024, 1)
topk_gather_kernel(const float* __restrict__ values,
                   const int* __restrict__ kp,
                   float* __restrict__ out) {
    const int tid  = threadIdx.x;
    const int lane = tid & 31;
    const int wid  = tid >> 5;
    const float ISD = 0.03125f;  // 1/sqrt(1024)

    __shared__ float s_red[32];
    __shared__ int   s_redi[32];
    __shared__ float s_M, s_S;
    __shared__ int   s_rows[32];

    // Load all 32768 scores into the block's register file (float4 loads).
    const float4* sc4 = (const float4*)g_scores;
    float4 v[8];
#pragma unroll
    for (int j = 0; j < 8; j++) v[j] = sc4[j * 1024 + tid];

    // ---- global max ----
    float m = -FLT_MAX;
#pragma unroll
    for (int j = 0; j < 8; j++) {
        m = fmaxf(m, fmaxf(fmaxf(v[j].x, v[j].y), fmaxf(v[j].z, v[j].w)));
    }
#pragma unroll
    for (int off = 16; off; off >>= 1) m = fmaxf(m, __shfl_xor_sync(0xffffffffu, m, off));
    if (lane == 0) s_red[wid] = m;
    __syncthreads();
    if (wid == 0) {
        float mm = s_red[lane];
#pragma unroll
        for (int off = 16; off; off >>= 1) mm = fmaxf(mm, __shfl_xor_sync(0xffffffffu, mm, off));
        if (lane == 0) s_M = mm;
    }
    __syncthreads();
    const float M = s_M;

    // ---- sum of exp (fast MUFU exp; accuracy ~1e-6, tolerance is 1e-3) ----
    float ssum = 0.f;
#pragma unroll
    for (int j = 0; j < 8; j++) {
        ssum += __expf((v[j].x - M) * ISD);
        ssum += __expf((v[j].y - M) * ISD);
        ssum += __expf((v[j].z - M) * ISD);
        ssum += __expf((v[j].w - M) * ISD);
    }
#pragma unroll
    for (int off = 16; off; off >>= 1) ssum += __shfl_xor_sync(0xffffffffu, ssum, off);
    if (lane == 0) s_red[wid] = ssum;
    __syncthreads();
    if (wid == 0) {
        float ss = s_red[lane];
#pragma unroll
        for (int off = 16; off; off >>= 1) ss += __shfl_xor_sync(0xffffffffu, ss, off);
        if (lane == 0) s_S = ss;
    }
    __syncthreads();
    const float S = s_S;

    const int k = *kp;

    // ---- k iterative argmax passes, register-local ----
    for (int t = 0; t < k; t++) {
        // local scan, ascending index order so ties pick the smallest index
        float best = -FLT_MAX;
        int bidx = 0x7fffffff;
#pragma unroll
        for (int j = 0; j < 8; j++) {
            const float a0 = v[j].x, a1 = v[j].y, a2 = v[j].z, a3 = v[j].w;
            const int base = j * 4096 + tid * 4;
            if (a0 > best) { best = a0; bidx = base + 0; }
            if (a1 > best) { best = a1; bidx = base + 1; }
            if (a2 > best) { best = a2; bidx = base + 2; }
            if (a3 > best) { best = a3; bidx = base + 3; }
        }
#pragma unroll
        for (int off = 16; off; off >>= 1) {
            float ov = __shfl_xor_sync(0xffffffffu, best, off);
            int   oi = __shfl_xor_sync(0xffffffffu, bidx, off);
            if (ov > best || (ov == best && oi < bidx)) { best = ov; bidx = oi; }
        }
        if (lane == 0) { s_red[wid] = best; s_redi[wid] = bidx; }
        __syncthreads();
        if (wid == 0) {
            float bb = s_red[lane];
            int   bi = s_redi[lane];
#pragma unroll
            for (int off = 16; off; off >>= 1) {
                float ov = __shfl_xor_sync(0xffffffffu, bb, off);
                int   oi = __shfl_xor_sync(0xffffffffu, bi, off);
                if (ov > bb || (ov == bb && oi < bi)) { bb = ov; bi = oi; }
            }
            if (lane == 0) {
                s_rows[t] = bi;
                out[(size_t)k * DDIM + t] = __expf((bb - M) * ISD) / S;
            }
        }
        __syncthreads();
        const int win = s_rows[t];
        if (((win >> 2) & 1023) == tid) {
            const int wj = win >> 12;
            const int wc = win & 3;
#pragma unroll
            for (int j = 0; j < 8; j++) {
                if (j == wj) {
                    if (wc == 0) v[j].x = -FLT_MAX;
                    else if (wc == 1) v[j].y = -FLT_MAX;
                    else if (wc == 2) v[j].z = -FLT_MAX;
                    else v[j].w = -FLT_MAX;
                }
            }
        }
        // no extra barrier: removal is register-local; s_rows[t] is stable
        // until the next iteration's post-reduction barrier has passed.
    }

    // ---- gather selected value rows, float4, flattened over all threads ----
    const float4* val4 = (const float4*)values;
    float4* out4 = (float4*)out;
    const int total4 = k * 256;            // k rows * 256 float4 per row
    for (int e = tid; e < total4; e += 1024) {
        const int t = e >> 8;              // which of the k winners
        const int c = e & 255;             // float4 column within the row
        const int r = s_rows[t];           // winner's key/value row index
        out4[(size_t)t * 256 + c] = val4[(size_t)r * 256 + c];
    }
}

// ---------------------------------------------------------------------------
extern "C" void kernel_launch(void* const* d_in, const int* in_sizes, int n_in,
                              void* d_out, int out_size) {
    const float* query  = (const float*)d_in[0];   // [1024]
    const float* keys   = (const float*)d_in[1];   // [32768,1024]
    const float* values = (const float*)d_in[2];   // [32768,1024]
    const float* Wq     = (const float*)d_in[3];   // [1024,1024]
    const float* bq     = (const float*)d_in[4];   // [1024]

    const int* kp;
    if (n_in >= 6) {
        kp = (const int*)d_in[5];
    } else {
        void* p = nullptr;
        cudaGetSymbolAddress(&p, g_defk);
        kp = (const int*)p;
    }

    float* out = (float*)d_out;

    // K1: block per row
    qproj_kernel<<<DDIM, 256>>>(query, Wq, bq);
    // K2: 32768 warps -> 4096 blocks x 256 threads
    scores_kernel<<<4096, 256>>>(keys);
    // K3: one block, 1024 threads
    topk_gather_kernel<<<1, 1024>>>(values, kp, out);
    (void)in_sizes; (void)out_size;
}